// round 3
// baseline (speedup 1.0000x reference)
#include <cuda_runtime.h>
#include <cuda_bf16.h>
#include <cstdint>

#define M_Q 4096
#define KDIM 512
#define NDB 50000
#define NSEG 8
#define SEGROWS 6272
#define NPAD (NSEG*SEGROWS)
#define NCHUNKS (SEGROWS/64)
#define NCAND 16
#define NPRE 32
#define ROWB 1040

#define OFF_A 0
#define OFF_B0 66560
#define OFF_B1 133120
#define OFF_SC 199680
#define OFF_TV 216320
#define OFF_TI 220416
#define SMEM_TOTAL 224512

__device__ __nv_bfloat16 g_Xbf[(size_t)M_Q*KDIM];
__device__ __nv_bfloat16 g_DBbf[(size_t)NPAD*KDIM];
__device__ float g_dbnorm[NPAD];
__device__ float g_cv[(size_t)M_Q*NSEG*NCAND];
__device__ int   g_ci[(size_t)M_Q*NSEG*NCAND];

__device__ __forceinline__ void cp16(void* dst, const void* src) {
    unsigned s = (unsigned)__cvta_generic_to_shared(dst);
    asm volatile("cp.async.cg.shared.global [%0], [%1], 16;\n" :: "r"(s), "l"(src));
}

__device__ __forceinline__ void mma16816(float* c,
    unsigned a0, unsigned a1, unsigned a2, unsigned a3, unsigned b0, unsigned b1) {
    asm volatile("mma.sync.aligned.m16n8k16.row.col.f32.bf16.bf16.f32 "
        "{%0,%1,%2,%3}, {%4,%5,%6,%7}, {%8,%9}, {%0,%1,%2,%3};\n"
        : "+f"(c[0]), "+f"(c[1]), "+f"(c[2]), "+f"(c[3])
        : "r"(a0), "r"(a1), "r"(a2), "r"(a3), "r"(b0), "r"(b1));
}

__global__ void conv_x_kernel(const float* __restrict__ x) {
    int i = blockIdx.x*blockDim.x + threadIdx.x;
    if (i < M_Q*KDIM) g_Xbf[i] = __float2bfloat16(x[i]);
}

__global__ void conv_db_kernel(const float* __restrict__ db) {
    int r = blockIdx.x;
    int tid = threadIdx.x;      // 128
    __shared__ float wsum[4];
    if (r < NDB) {
        const float* row = db + (size_t)r*KDIM;
        float acc = 0.f;
        for (int k = tid; k < KDIM; k += 128) {
            float v = row[k];
            g_DBbf[(size_t)r*KDIM + k] = __float2bfloat16(v);
            acc += v*v;
        }
        #pragma unroll
        for (int o = 16; o; o >>= 1) acc += __shfl_xor_sync(0xffffffffu, acc, o);
        if ((tid & 31) == 0) wsum[tid >> 5] = acc;
        __syncthreads();
        if (tid == 0) g_dbnorm[r] = wsum[0]+wsum[1]+wsum[2]+wsum[3];
    } else {
        for (int k = tid; k < KDIM; k += 128)
            g_DBbf[(size_t)r*KDIM + k] = __float2bfloat16(0.f);
        if (tid == 0) g_dbnorm[r] = __int_as_float(0x7f800000);
    }
}

// grid(64 m-tiles, 8 segments), 256 threads, 1 CTA/SM
__global__ __launch_bounds__(256, 1)
void score_topk_kernel() {
    extern __shared__ char sm[];
    char*  As     = sm + OFF_A;
    float* scores = (float*)(sm + OFF_SC);   // [64][65]
    float* topv   = (float*)(sm + OFF_TV);   // [64][16] ascending
    int*   topi   = (int*)  (sm + OFF_TI);

    const int tid  = threadIdx.x;
    const int warp = tid >> 5, lane = tid & 31;
    const int wm = warp >> 1, wn = warp & 1;
    const int grp = lane >> 2, qid = lane & 3;
    const int m0 = blockIdx.x * 64;
    const int segbase = blockIdx.y * SEGROWS;

    for (int i = tid; i < 64*64; i += 256) {
        int r = i >> 6, c = i & 63;
        cp16(As + r*ROWB + c*16, g_Xbf + (size_t)(m0 + r)*KDIM + c*8);
    }
    for (int i = tid; i < 64*64; i += 256) {
        int r = i >> 6, c = i & 63;
        cp16(sm + OFF_B0 + r*ROWB + c*16, g_DBbf + (size_t)(segbase + r)*KDIM + c*8);
    }
    asm volatile("cp.async.commit_group;\n" ::: "memory");
    for (int i = tid; i < 64*NCAND; i += 256) {
        topv[i] = __int_as_float(0x7f800000);
        topi[i] = -1;
    }
    asm volatile("cp.async.wait_group 0;\n" ::: "memory");
    __syncthreads();

    const char* Apt = As + (wm*16 + grp)*ROWB + qid*4;
    const int mA = wm*16 + grp, mB = mA + 8;

    for (int chunk = 0; chunk < NCHUNKS; ++chunk) {
        const char* Bcur = sm + ((chunk & 1) ? OFF_B1 : OFF_B0);
        char*       Bnxt = sm + ((chunk & 1) ? OFF_B0 : OFF_B1);
        if (chunk + 1 < NCHUNKS) {
            int n0n = segbase + (chunk + 1)*64;
            for (int i = tid; i < 64*64; i += 256) {
                int r = i >> 6, c = i & 63;
                cp16(Bnxt + r*ROWB + c*16, g_DBbf + (size_t)(n0n + r)*KDIM + c*8);
            }
            asm volatile("cp.async.commit_group;\n" ::: "memory");
            asm volatile("cp.async.wait_group 1;\n" ::: "memory");
        } else {
            asm volatile("cp.async.wait_group 0;\n" ::: "memory");
        }
        __syncthreads();   // B(chunk) ready; prev selection done

        float acc[4][4];
        #pragma unroll
        for (int j = 0; j < 4; ++j)
            #pragma unroll
            for (int e = 0; e < 4; ++e) acc[j][e] = 0.f;

        const char* Bpt = Bcur + (wn*32 + grp)*ROWB + qid*4;
        #pragma unroll 4
        for (int ks = 0; ks < 32; ++ks) {
            const int kb = ks * 32;
            unsigned a0 = *(const unsigned*)(Apt + kb);
            unsigned a1 = *(const unsigned*)(Apt + kb + 8*ROWB);
            unsigned a2 = *(const unsigned*)(Apt + kb + 16);
            unsigned a3 = *(const unsigned*)(Apt + kb + 8*ROWB + 16);
            #pragma unroll
            for (int j = 0; j < 4; ++j) {
                unsigned b0 = *(const unsigned*)(Bpt + kb + j*8*ROWB);
                unsigned b1 = *(const unsigned*)(Bpt + kb + j*8*ROWB + 16);
                mma16816(acc[j], a0, a1, a2, a3, b0, b1);
            }
        }

        const int nbase = segbase + chunk*64;
        #pragma unroll
        for (int j = 0; j < 4; ++j) {
            int nl = wn*32 + j*8 + qid*2;
            float nrm0 = __ldg(&g_dbnorm[nbase + nl]);
            float nrm1 = __ldg(&g_dbnorm[nbase + nl + 1]);
            scores[mA*65 + nl]     = nrm0 - 2.f*acc[j][0];
            scores[mA*65 + nl + 1] = nrm1 - 2.f*acc[j][1];
            scores[mB*65 + nl]     = nrm0 - 2.f*acc[j][2];
            scores[mB*65 + nl + 1] = nrm1 - 2.f*acc[j][3];
        }
        __syncthreads();   // scores complete

        if (tid < 64) {    // per-query serial top-16 insert
            float* tv = topv + tid*NCAND;
            int*   ti = topi + tid*NCAND;
            float worst = tv[NCAND-1];
            const float* srow = scores + tid*65;
            for (int j = 0; j < 64; ++j) {
                float s = srow[j];
                if (s < worst) {
                    int p = NCAND-1;
                    while (p > 0 && tv[p-1] > s) {
                        tv[p] = tv[p-1]; ti[p] = ti[p-1]; --p;
                    }
                    tv[p] = s; ti[p] = nbase + j;
                    worst = tv[NCAND-1];
                }
            }
        }
        // next-iter top sync orders selection before next score writes
    }
    __syncthreads();
    if (tid < 64) {
        size_t base = ((size_t)(m0 + tid)*NSEG + blockIdx.y)*NCAND;
        for (int i = 0; i < NCAND; ++i) {
            g_cv[base + i] = topv[tid*NCAND + i];
            g_ci[base + i] = topi[tid*NCAND + i];
        }
    }
}

// one block per query, 128 threads
__global__ __launch_bounds__(128)
void lle_kernel(const float* __restrict__ x, const float* __restrict__ db,
                float* __restrict__ out) {
    __shared__ float xs[512];
    __shared__ float nb[10*520];
    __shared__ float cv[128];
    __shared__ int   ci[128];
    __shared__ int   psel[NPRE];
    __shared__ float pd[NPRE];
    __shared__ float G[9][10];
    __shared__ float w[9];
    __shared__ int   sel[10];

    const int q = blockIdx.x, tid = threadIdx.x;
    const int warp = tid >> 5, lane = tid & 31;
    size_t cb = (size_t)q*NSEG*NCAND;
    cv[tid] = g_cv[cb + tid];
    ci[tid] = g_ci[cb + tid];
    for (int n = tid; n < 512; n += 128) xs[n] = x[(size_t)q*512 + n];
    __syncthreads();

    // ---- stage 1: approx preselect top-NPRE of 128 (any safe superset) ----
    if (tid == 0) {
        float bv[NPRE]; int bi[NPRE];
        #pragma unroll
        for (int i = 0; i < NPRE; ++i) { bv[i] = __int_as_float(0x7f800000); bi[i] = 0x7fffffff; }
        for (int c = 0; c < 128; ++c) {
            float v = cv[c]; int id = ci[c];
            if (v < bv[NPRE-1]) {
                int p = NPRE-1;
                while (p > 0 && bv[p-1] > v) {
                    bv[p] = bv[p-1]; bi[p] = bi[p-1]; --p;
                }
                bv[p] = v; bi[p] = id;
            }
        }
        #pragma unroll
        for (int i = 0; i < NPRE; ++i) psel[i] = bi[i];
    }
    __syncthreads();

    // ---- stage 2: EXACT fp32 rescore of NPRE candidates ----
    // warp w handles candidates [w*8, w*8+8); lane partials 16 terms each,
    // then 5-level pairwise tree reduce (error ~3e-5, below reference's own).
    for (int c = warp*8; c < warp*8 + 8; ++c) {
        const float* row = db + (size_t)psel[c]*512;
        float acc = 0.f;
        #pragma unroll
        for (int j = 0; j < 16; ++j) {
            int n = lane + 32*j;
            float v = row[n] - xs[n];
            acc = fmaf(v, v, acc);
        }
        #pragma unroll
        for (int o = 16; o; o >>= 1) acc += __shfl_xor_sync(0xffffffffu, acc, o);
        if (lane == 0) pd[c] = acc;
    }
    __syncthreads();

    // ---- stage 3: exact ordered top-10 by (d asc, idx asc) ----
    if (tid == 0) {
        float bv[10]; int bi[10];
        #pragma unroll
        for (int i = 0; i < 10; ++i) { bv[i] = __int_as_float(0x7f800000); bi[i] = 0x7fffffff; }
        for (int c = 0; c < NPRE; ++c) {
            float v = pd[c]; int id = psel[c];
            if (v < bv[9] || (v == bv[9] && id < bi[9])) {
                int p = 9;
                while (p > 0 && (bv[p-1] > v || (bv[p-1] == v && bi[p-1] > id))) {
                    bv[p] = bv[p-1]; bi[p] = bi[p-1]; --p;
                }
                bv[p] = v; bi[p] = id;
            }
        }
        #pragma unroll
        for (int i = 0; i < 10; ++i) sel[i] = bi[i];
    }
    __syncthreads();

    for (int r = 0; r < 10; ++r) {
        const float* row = db + (size_t)sel[r]*512;
        for (int n = tid; n < 512; n += 128) nb[r*520 + n] = row[n];
    }
    __syncthreads();

    if (tid < 90) {   // Gram: 81 ATA + 9 ATB, one 512-dot each
        float accv = 0.f;
        if (tid < 81) {
            int i = tid / 9, j = tid % 9;
            const float* ai = nb + (i+1)*520;
            const float* aj = nb + (j+1)*520;
            for (int n = 0; n < 512; ++n) {
                float f0 = nb[n];
                accv += (ai[n]-f0)*(aj[n]-f0);
            }
            G[i][j] = accv;
        } else {
            int i = tid - 81;
            const float* ai = nb + (i+1)*520;
            for (int n = 0; n < 512; ++n) {
                float f0 = nb[n];
                accv += (ai[n]-f0)*(xs[n]-f0);
            }
            G[i][9] = accv;
        }
    }
    __syncthreads();

    if (tid == 0) {   // 9x9 Gauss, partial pivoting
        for (int k = 0; k < 9; ++k) {
            int p = k;
            for (int r = k+1; r < 9; ++r)
                if (fabsf(G[r][k]) > fabsf(G[p][k])) p = r;
            if (p != k)
                for (int c = k; c < 10; ++c) {
                    float t = G[k][c]; G[k][c] = G[p][c]; G[p][c] = t;
                }
            float inv = 1.f / G[k][k];
            for (int r = k+1; r < 9; ++r) {
                float f = G[r][k] * inv;
                for (int c = k; c < 10; ++c) G[r][c] -= f*G[k][c];
            }
        }
        for (int k = 8; k >= 0; --k) {
            float s = G[k][9];
            for (int c = k+1; c < 9; ++c) s -= G[k][c]*w[c];
            w[k] = s / G[k][k];
        }
    }
    __syncthreads();

    float w0 = 1.f;
    #pragma unroll
    for (int k = 0; k < 9; ++k) w0 -= w[k];
    for (int n = tid; n < 512; n += 128) {
        float fuse = w0 * nb[n];
        #pragma unroll
        for (int k = 0; k < 9; ++k) fuse += w[k]*nb[(k+1)*520 + n];
        out[(size_t)q*512 + n] = 0.2f*xs[n] + 0.8f*fuse;
    }
}

extern "C" void kernel_launch(void* const* d_in, const int* in_sizes, int n_in,
                              void* d_out, int out_size) {
    const float* x  = (const float*)d_in[0];
    const float* db = (const float*)d_in[1];
    float* out = (float*)d_out;

    cudaFuncSetAttribute(score_topk_kernel,
        cudaFuncAttributeMaxDynamicSharedMemorySize, SMEM_TOTAL);

    conv_x_kernel<<<(M_Q*KDIM + 255)/256, 256>>>(x);
    conv_db_kernel<<<NPAD, 128>>>(db);
    score_topk_kernel<<<dim3(M_Q/64, NSEG), 256, SMEM_TOTAL>>>();
    lle_kernel<<<M_Q, 128>>>(x, db, out);
}

// round 5
// speedup vs baseline: 1.2807x; 1.2807x over previous
#include <cuda_runtime.h>
#include <cuda_bf16.h>
#include <cstdint>

#define M_Q 4096
#define KDIM 512
#define NDB 50000
#define NSEG 8
#define SEGROWS 6272
#define NPAD (NSEG*SEGROWS)
#define BM 128
#define BN 32
#define NCHUNKS (SEGROWS/BN)    // 196
#define NCAND 16
#define NPRE 32
#define ROWB 1040               // 512 bf16 + 16B pad: LDSM conflict-free

#define SM_A   0                // 128 x 1040 = 133120
#define SM_B0  133120           // 32 x 1040 = 33280
#define SM_B1  166400
#define SM_SC  199680           // scores[128][33] fp32 = 16896
#define SM_NRM 216576           // norm staging [2][32] fp32 = 256
#define SMEM_SC_TOTAL 216832

__device__ __nv_bfloat16 g_Xbf[(size_t)M_Q*KDIM];
__device__ __nv_bfloat16 g_DBbf[(size_t)NPAD*KDIM];
__device__ float g_dbnorm[NPAD];
__device__ float g_cv[(size_t)M_Q*NSEG*NCAND];
__device__ int   g_ci[(size_t)M_Q*NSEG*NCAND];

__device__ __forceinline__ unsigned smem_u32(const void* p) {
    unsigned a;
    asm("{ .reg .u64 t; cvta.to.shared.u64 t, %1; cvt.u32.u64 %0, t; }"
        : "=r"(a) : "l"(p));
    return a;
}
__device__ __forceinline__ void cp16(unsigned dsts, const void* src) {
    asm volatile("cp.async.cg.shared.global [%0], [%1], 16;\n" :: "r"(dsts), "l"(src));
}
__device__ __forceinline__ void ldsm4(unsigned& r0, unsigned& r1, unsigned& r2,
                                      unsigned& r3, unsigned addr) {
    asm volatile("ldmatrix.sync.aligned.m8n8.x4.shared.b16 {%0,%1,%2,%3}, [%4];"
                 : "=r"(r0), "=r"(r1), "=r"(r2), "=r"(r3) : "r"(addr));
}
__device__ __forceinline__ void mma16816(float* c,
    unsigned a0, unsigned a1, unsigned a2, unsigned a3, unsigned b0, unsigned b1) {
    asm volatile("mma.sync.aligned.m16n8k16.row.col.f32.bf16.bf16.f32 "
        "{%0,%1,%2,%3}, {%4,%5,%6,%7}, {%8,%9}, {%0,%1,%2,%3};\n"
        : "+f"(c[0]), "+f"(c[1]), "+f"(c[2]), "+f"(c[3])
        : "r"(a0), "r"(a1), "r"(a2), "r"(a3), "r"(b0), "r"(b1));
}

// ---------------- prep ----------------
__global__ void conv_x_kernel(const float* __restrict__ x) {
    int i = blockIdx.x*blockDim.x + threadIdx.x;
    if (i < M_Q*KDIM) g_Xbf[i] = __float2bfloat16(x[i]);
}

__global__ void conv_db_kernel(const float* __restrict__ db) {
    int r = blockIdx.x;
    int tid = threadIdx.x;      // 128
    __shared__ float wsum[4];
    if (r < NDB) {
        const float* row = db + (size_t)r*KDIM;
        float acc = 0.f;
        for (int k = tid; k < KDIM; k += 128) {
            float v = row[k];
            g_DBbf[(size_t)r*KDIM + k] = __float2bfloat16(v);
            acc += v*v;
        }
        #pragma unroll
        for (int o = 16; o; o >>= 1) acc += __shfl_xor_sync(0xffffffffu, acc, o);
        if ((tid & 31) == 0) wsum[tid >> 5] = acc;
        __syncthreads();
        if (tid == 0) g_dbnorm[r] = wsum[0]+wsum[1]+wsum[2]+wsum[3];
    } else {
        for (int k = tid; k < KDIM; k += 128)
            g_DBbf[(size_t)r*KDIM + k] = __float2bfloat16(0.f);
        if (tid == 0) g_dbnorm[r] = __int_as_float(0x7f800000);
    }
}

// ---------------- fused score + top-16 ----------------
__device__ __forceinline__ void select32(const float* srow, const float* nb,
                                         int base, float* tv, int* ti) {
    float worst = tv[NCAND-1];
    #pragma unroll
    for (int j = 0; j < 32; ++j) {
        float v = nb[j] - 2.f*srow[j];
        if (v < worst) {
            int p = NCAND-1;
            while (p > 0 && tv[p-1] > v) { tv[p] = tv[p-1]; ti[p] = ti[p-1]; --p; }
            tv[p] = v; ti[p] = base + j;
            worst = tv[NCAND-1];
        }
    }
}

__global__ __launch_bounds__(256, 1)
void score_topk_kernel() {
    extern __shared__ char sm[];
    const int tid = threadIdx.x;
    const int warp = tid >> 5, lane = tid & 31;
    const int wm = warp >> 1, wn = warp & 1;
    const int m0 = blockIdx.x * BM;
    const int segbase = blockIdx.y * SEGROWS;
    const unsigned sbase = smem_u32(sm);
    float* scS  = (float*)(sm + SM_SC);
    float* nrmS = (float*)(sm + SM_NRM);

    // prologue: A tile (resident) + B chunk 0, one commit group
    for (int i = tid; i < BM*64; i += 256) {
        int r = i >> 6, c16 = i & 63;
        cp16(sbase + SM_A + r*ROWB + c16*16, g_Xbf + (size_t)(m0 + r)*KDIM + c16*8);
    }
    for (int i = tid; i < BN*64; i += 256) {
        int r = i >> 6, c16 = i & 63;
        cp16(sbase + SM_B0 + r*ROWB + c16*16, g_DBbf + (size_t)(segbase + r)*KDIM + c16*8);
    }
    asm volatile("cp.async.commit_group;\n" ::: "memory");
    if (tid < 32) nrmS[tid] = __ldg(&g_dbnorm[segbase + tid]);   // chunk0 -> slot0

    float tv[NCAND]; int ti[NCAND];
    #pragma unroll
    for (int i = 0; i < NCAND; ++i) { tv[i] = __int_as_float(0x7f800000); ti[i] = -1; }

    // warp-constant LDSM base addresses (lane-mapped for m8n8.x4)
    const unsigned aBase = sbase + SM_A
        + (unsigned)((wm*32 + (lane & 15))*ROWB + (lane >> 4)*16);
    const unsigned bRow = (unsigned)((wn*16 + (lane & 15))*ROWB + (lane >> 4)*16);

    for (int c = 0; c < NCHUNKS; ++c) {
        asm volatile("cp.async.wait_group 0;\n" ::: "memory");
        __syncthreads();          // B[c] ready, scores[c-1] written

        if (c + 1 < NCHUNKS) {    // prefetch B[c+1] first: DMA under compute
            unsigned nxt = sbase + ((c & 1) ? SM_B0 : SM_B1);
            const __nv_bfloat16* src = g_DBbf + (size_t)(segbase + (c+1)*BN)*KDIM;
            for (int i = tid; i < BN*64; i += 256) {
                int r = i >> 6, c16 = i & 63;
                cp16(nxt + r*ROWB + c16*16, src + (size_t)r*KDIM + c16*8);
            }
            asm volatile("cp.async.commit_group;\n" ::: "memory");
        }

        float acc[2][2][4];
        #pragma unroll
        for (int mt = 0; mt < 2; ++mt)
            #pragma unroll
            for (int nt = 0; nt < 2; ++nt)
                #pragma unroll
                for (int e = 0; e < 4; ++e) acc[mt][nt][e] = 0.f;

        const unsigned bBase = sbase + ((c & 1) ? SM_B1 : SM_B0) + bRow;
        #pragma unroll 8
        for (int ks = 0; ks < 32; ++ks) {
            unsigned a0[4], a1[4], b[4];
            ldsm4(a0[0], a0[1], a0[2], a0[3], aBase + ks*32);
            ldsm4(a1[0], a1[1], a1[2], a1[3], aBase + 16*ROWB + ks*32);
            ldsm4(b[0], b[1], b[2], b[3], bBase + ks*32);
            mma16816(acc[0][0], a0[0], a0[1], a0[2], a0[3], b[0], b[2]);
            mma16816(acc[0][1], a0[0], a0[1], a0[2], a0[3], b[1], b[3]);
            mma16816(acc[1][0], a1[0], a1[1], a1[2], a1[3], b[0], b[2]);
            mma16816(acc[1][1], a1[0], a1[1], a1[2], a1[3], b[1], b[3]);
        }

        // select chunk c-1 (overlaps other warps' MMA tails)
        if (c > 0 && tid < 128)
            select32(scS + tid*33, nrmS + ((c-1) & 1)*32,
                     segbase + (c-1)*BN, tv, ti);
        __syncthreads();          // selection done; scores buffer free

        #pragma unroll
        for (int mt = 0; mt < 2; ++mt)
            #pragma unroll
            for (int nt = 0; nt < 2; ++nt)
                #pragma unroll
                for (int e = 0; e < 4; ++e) {
                    int row = wm*32 + mt*16 + (lane >> 2) + ((e >> 1) << 3);
                    int col = wn*16 + nt*8 + ((lane & 3) << 1) + (e & 1);
                    scS[row*33 + col] = acc[mt][nt][e];
                }
        if (c >= 1 && tid < 32)   // stage norms for chunk c -> slot c&1
            nrmS[(c & 1)*32 + tid] = __ldg(&g_dbnorm[segbase + c*BN + tid]);
    }
    __syncthreads();
    if (tid < 128) {
        select32(scS + tid*33, nrmS + ((NCHUNKS-1) & 1)*32,
                 segbase + (NCHUNKS-1)*BN, tv, ti);
        size_t base = ((size_t)(m0 + tid)*NSEG + blockIdx.y)*NCAND;
        #pragma unroll
        for (int i = 0; i < NCAND; ++i) { g_cv[base + i] = tv[i]; g_ci[base + i] = ti[i]; }
    }
}

// ---------------- LLE (unchanged, proven) ----------------
__global__ __launch_bounds__(128)
void lle_kernel(const float* __restrict__ x, const float* __restrict__ db,
                float* __restrict__ out) {
    __shared__ float xs[512];
    __shared__ float nb[10*520];
    __shared__ float cv[128];
    __shared__ int   ci[128];
    __shared__ int   psel[NPRE];
    __shared__ float pd[NPRE];
    __shared__ float G[9][10];
    __shared__ float w[9];
    __shared__ int   sel[10];

    const int q = blockIdx.x, tid = threadIdx.x;
    const int warp = tid >> 5, lane = tid & 31;
    size_t cb = (size_t)q*NSEG*NCAND;
    cv[tid] = g_cv[cb + tid];
    ci[tid] = g_ci[cb + tid];
    for (int n = tid; n < 512; n += 128) xs[n] = x[(size_t)q*512 + n];
    __syncthreads();

    if (tid == 0) {   // approx preselect top-NPRE of 128
        float bv[NPRE]; int bi[NPRE];
        #pragma unroll
        for (int i = 0; i < NPRE; ++i) { bv[i] = __int_as_float(0x7f800000); bi[i] = 0x7fffffff; }
        for (int c = 0; c < 128; ++c) {
            float v = cv[c]; int id = ci[c];
            if (v < bv[NPRE-1]) {
                int p = NPRE-1;
                while (p > 0 && bv[p-1] > v) { bv[p] = bv[p-1]; bi[p] = bi[p-1]; --p; }
                bv[p] = v; bi[p] = id;
            }
        }
        #pragma unroll
        for (int i = 0; i < NPRE; ++i) psel[i] = bi[i];
    }
    __syncthreads();

    for (int c = warp*8; c < warp*8 + 8; ++c) {   // exact fp32 rescore
        const float* row = db + (size_t)psel[c]*512;
        float acc = 0.f;
        #pragma unroll
        for (int j = 0; j < 16; ++j) {
            int n = lane + 32*j;
            float v = row[n] - xs[n];
            acc = fmaf(v, v, acc);
        }
        #pragma unroll
        for (int o = 16; o; o >>= 1) acc += __shfl_xor_sync(0xffffffffu, acc, o);
        if (lane == 0) pd[c] = acc;
    }
    __syncthreads();

    if (tid == 0) {   // exact ordered top-10 (d asc, idx asc)
        float bv[10]; int bi[10];
        #pragma unroll
        for (int i = 0; i < 10; ++i) { bv[i] = __int_as_float(0x7f800000); bi[i] = 0x7fffffff; }
        for (int c = 0; c < NPRE; ++c) {
            float v = pd[c]; int id = psel[c];
            if (v < bv[9] || (v == bv[9] && id < bi[9])) {
                int p = 9;
                while (p > 0 && (bv[p-1] > v || (bv[p-1] == v && bi[p-1] > id))) {
                    bv[p] = bv[p-1]; bi[p] = bi[p-1]; --p;
                }
                bv[p] = v; bi[p] = id;
            }
        }
        #pragma unroll
        for (int i = 0; i < 10; ++i) sel[i] = bi[i];
    }
    __syncthreads();

    for (int r = 0; r < 10; ++r) {
        const float* row = db + (size_t)sel[r]*512;
        for (int n = tid; n < 512; n += 128) nb[r*520 + n] = row[n];
    }
    __syncthreads();

    if (tid < 90) {
        float accv = 0.f;
        if (tid < 81) {
            int i = tid / 9, j = tid % 9;
            const float* ai = nb + (i+1)*520;
            const float* aj = nb + (j+1)*520;
            for (int n = 0; n < 512; ++n) {
                float f0 = nb[n];
                accv += (ai[n]-f0)*(aj[n]-f0);
            }
            G[i][j] = accv;
        } else {
            int i = tid - 81;
            const float* ai = nb + (i+1)*520;
            for (int n = 0; n < 512; ++n) {
                float f0 = nb[n];
                accv += (ai[n]-f0)*(xs[n]-f0);
            }
            G[i][9] = accv;
        }
    }
    __syncthreads();

    if (tid == 0) {
        for (int k = 0; k < 9; ++k) {
            int p = k;
            for (int r = k+1; r < 9; ++r)
                if (fabsf(G[r][k]) > fabsf(G[p][k])) p = r;
            if (p != k)
                for (int c = k; c < 10; ++c) {
                    float t = G[k][c]; G[k][c] = G[p][c]; G[p][c] = t;
                }
            float inv = 1.f / G[k][k];
            for (int r = k+1; r < 9; ++r) {
                float f = G[r][k] * inv;
                for (int c = k; c < 10; ++c) G[r][c] -= f*G[k][c];
            }
        }
        for (int k = 8; k >= 0; --k) {
            float s = G[k][9];
            for (int c = k+1; c < 9; ++c) s -= G[k][c]*w[c];
            w[k] = s / G[k][k];
        }
    }
    __syncthreads();

    float w0 = 1.f;
    #pragma unroll
    for (int k = 0; k < 9; ++k) w0 -= w[k];
    for (int n = tid; n < 512; n += 128) {
        float fuse = w0 * nb[n];
        #pragma unroll
        for (int k = 0; k < 9; ++k) fuse += w[k]*nb[(k+1)*520 + n];
        out[(size_t)q*512 + n] = 0.2f*xs[n] + 0.8f*fuse;
    }
}

extern "C" void kernel_launch(void* const* d_in, const int* in_sizes, int n_in,
                              void* d_out, int out_size) {
    const float* x  = (const float*)d_in[0];
    const float* db = (const float*)d_in[1];
    float* out = (float*)d_out;

    cudaFuncSetAttribute(score_topk_kernel,
        cudaFuncAttributeMaxDynamicSharedMemorySize, SMEM_SC_TOTAL);

    conv_x_kernel<<<(M_Q*KDIM + 255)/256, 256>>>(x);
    conv_db_kernel<<<NPAD, 128>>>(db);
    score_topk_kernel<<<dim3(M_Q/BM, NSEG), 256, SMEM_SC_TOTAL>>>();
    lle_kernel<<<M_Q, 128>>>(x, db, out);
}

// round 6
// speedup vs baseline: 1.4904x; 1.1637x over previous
#include <cuda_runtime.h>
#include <cuda_bf16.h>
#include <cstdint>

#define M_Q 4096
#define KDIM 512
#define NDB 50000
#define NSEG 8
#define SEGROWS 6272
#define NPAD (NSEG*SEGROWS)
#define BM 128
#define BN 64
#define NCHUNKS (SEGROWS/BN)    // 98
#define NCAND 16
#define NPRE 32
#define ROWB 528                // 512 int8 + 16B pad: LDSM conflict-free

#define QSC  23.090909f         // 127/5.5
#define DEQ2 (2.0f/(QSC*QSC))

#define SM_A   0                // 128 x 528 = 67584
#define SM_B0  67584            // 64 x 528 = 33792
#define SM_B1  101376
#define SM_SC  135168           // scores[128][65] fp32 = 33280
#define SM_NRM 168448           // norm staging [2][64] fp32 = 512
#define SMEM_SC_TOTAL 168960

__device__ int8_t g_Xq[(size_t)M_Q*KDIM];
__device__ int8_t g_DBq[(size_t)NPAD*KDIM];
__device__ float g_dbnorm[NPAD];
__device__ float g_cv[(size_t)M_Q*NSEG*NCAND];
__device__ int   g_ci[(size_t)M_Q*NSEG*NCAND];

__device__ __forceinline__ unsigned smem_u32(const void* p) {
    unsigned a;
    asm("{ .reg .u64 t; cvta.to.shared.u64 t, %1; cvt.u32.u64 %0, t; }"
        : "=r"(a) : "l"(p));
    return a;
}
__device__ __forceinline__ void cp16(unsigned dsts, const void* src) {
    asm volatile("cp.async.cg.shared.global [%0], [%1], 16;\n" :: "r"(dsts), "l"(src));
}
__device__ __forceinline__ void ldsm4(unsigned& r0, unsigned& r1, unsigned& r2,
                                      unsigned& r3, unsigned addr) {
    asm volatile("ldmatrix.sync.aligned.m8n8.x4.shared.b16 {%0,%1,%2,%3}, [%4];"
                 : "=r"(r0), "=r"(r1), "=r"(r2), "=r"(r3) : "r"(addr));
}
__device__ __forceinline__ void imma16832(int* c,
    unsigned a0, unsigned a1, unsigned a2, unsigned a3, unsigned b0, unsigned b1) {
    asm volatile("mma.sync.aligned.m16n8k32.row.col.s32.s8.s8.s32 "
        "{%0,%1,%2,%3}, {%4,%5,%6,%7}, {%8,%9}, {%0,%1,%2,%3};\n"
        : "+r"(c[0]), "+r"(c[1]), "+r"(c[2]), "+r"(c[3])
        : "r"(a0), "r"(a1), "r"(a2), "r"(a3), "r"(b0), "r"(b1));
}

// ---------------- prep: fp32 -> int8 (scale 127/5.5) + exact fp32 norms ----------------
__global__ void conv_x_kernel(const float* __restrict__ x) {
    int i = blockIdx.x*blockDim.x + threadIdx.x;
    if (i < M_Q*KDIM) {
        float v = fminf(fmaxf(x[i], -5.5f), 5.5f);
        g_Xq[i] = (int8_t)__float2int_rn(v * QSC);
    }
}

__global__ void conv_db_kernel(const float* __restrict__ db) {
    int r = blockIdx.x;
    int tid = threadIdx.x;      // 128
    __shared__ float wsum[4];
    if (r < NDB) {
        const float* row = db + (size_t)r*KDIM;
        float acc = 0.f;
        for (int k = tid; k < KDIM; k += 128) {
            float v = row[k];
            acc += v*v;
            float c = fminf(fmaxf(v, -5.5f), 5.5f);
            g_DBq[(size_t)r*KDIM + k] = (int8_t)__float2int_rn(c * QSC);
        }
        #pragma unroll
        for (int o = 16; o; o >>= 1) acc += __shfl_xor_sync(0xffffffffu, acc, o);
        if ((tid & 31) == 0) wsum[tid >> 5] = acc;
        __syncthreads();
        if (tid == 0) g_dbnorm[r] = wsum[0]+wsum[1]+wsum[2]+wsum[3];
    } else {
        for (int k = tid; k < KDIM; k += 128)
            g_DBq[(size_t)r*KDIM + k] = 0;
        if (tid == 0) g_dbnorm[r] = __int_as_float(0x7f800000);
    }
}

// ---------------- fused int8 score + top-16 ----------------
__device__ __forceinline__ void select64(const float* srow, const float* nb,
                                         int base, float* tv, int* ti) {
    float worst = tv[NCAND-1];
    #pragma unroll
    for (int j = 0; j < 64; ++j) {
        float v = nb[j] - DEQ2*srow[j];
        if (v < worst) {
            int p = NCAND-1;
            while (p > 0 && tv[p-1] > v) { tv[p] = tv[p-1]; ti[p] = ti[p-1]; --p; }
            tv[p] = v; ti[p] = base + j;
            worst = tv[NCAND-1];
        }
    }
}

__global__ __launch_bounds__(512, 1)
void score_topk_kernel() {
    extern __shared__ char sm[];
    const int tid = threadIdx.x;
    const int warp = tid >> 5, lane = tid & 31;
    const int wm = warp >> 2, wn = warp & 3;   // 4m x 4n warps
    const int m0 = blockIdx.x * BM;
    const int segbase = blockIdx.y * SEGROWS;
    const unsigned sbase = smem_u32(sm);
    float* scS  = (float*)(sm + SM_SC);
    float* nrmS = (float*)(sm + SM_NRM);

    // prologue: A tile (resident) + B chunk 0
    for (int i = tid; i < BM*32; i += 512) {
        int r = i >> 5, c16 = i & 31;
        cp16(sbase + SM_A + r*ROWB + c16*16, g_Xq + (size_t)(m0 + r)*KDIM + c16*16);
    }
    for (int i = tid; i < BN*32; i += 512) {
        int r = i >> 5, c16 = i & 31;
        cp16(sbase + SM_B0 + r*ROWB + c16*16, g_DBq + (size_t)(segbase + r)*KDIM + c16*16);
    }
    asm volatile("cp.async.commit_group;\n" ::: "memory");
    if (tid < 64) nrmS[tid] = __ldg(&g_dbnorm[segbase + tid]);   // chunk0 -> slot0

    float tv[NCAND]; int ti[NCAND];
    #pragma unroll
    for (int i = 0; i < NCAND; ++i) { tv[i] = __int_as_float(0x7f800000); ti[i] = -1; }

    // LDSM bases (canonical sm80 int8 fragment addressing)
    const unsigned aBase = sbase + SM_A
        + (unsigned)((wm*32 + (lane & 15))*ROWB + (lane >> 4)*16);
    const unsigned bRow = (unsigned)(
        (wn*16 + ((lane >> 4) << 3) + (lane & 7))*ROWB + ((lane >> 3) & 1)*16);

    for (int c = 0; c < NCHUNKS; ++c) {
        asm volatile("cp.async.wait_group 0;\n" ::: "memory");
        __syncthreads();          // B[c] ready; scores[c-1] visible

        if (c + 1 < NCHUNKS) {    // prefetch B[c+1]: DMA rides under compute
            unsigned nxt = sbase + ((c & 1) ? SM_B0 : SM_B1);
            const int8_t* src = g_DBq + (size_t)(segbase + (c+1)*BN)*KDIM;
            for (int i = tid; i < BN*32; i += 512) {
                int r = i >> 5, c16 = i & 31;
                cp16(nxt + r*ROWB + c16*16, src + (size_t)r*KDIM + c16*16);
            }
            asm volatile("cp.async.commit_group;\n" ::: "memory");
        }

        int acc[2][2][4];
        #pragma unroll
        for (int mt = 0; mt < 2; ++mt)
            #pragma unroll
            for (int nt = 0; nt < 2; ++nt)
                #pragma unroll
                for (int e = 0; e < 4; ++e) acc[mt][nt][e] = 0;

        const unsigned bBase = sbase + ((c & 1) ? SM_B1 : SM_B0) + bRow;
        #pragma unroll 8
        for (int ks = 0; ks < 16; ++ks) {       // 16 x k32 = K512
            unsigned a0[4], a1[4], b[4];
            ldsm4(a0[0], a0[1], a0[2], a0[3], aBase + ks*32);
            ldsm4(a1[0], a1[1], a1[2], a1[3], aBase + 16*ROWB + ks*32);
            ldsm4(b[0], b[1], b[2], b[3], bBase + ks*32);
            imma16832(acc[0][0], a0[0], a0[1], a0[2], a0[3], b[0], b[1]);
            imma16832(acc[0][1], a0[0], a0[1], a0[2], a0[3], b[2], b[3]);
            imma16832(acc[1][0], a1[0], a1[1], a1[2], a1[3], b[0], b[1]);
            imma16832(acc[1][1], a1[0], a1[1], a1[2], a1[3], b[2], b[3]);
        }

        // select chunk c-1 while other warps finish MMA
        if (c > 0 && tid < 128)
            select64(scS + tid*65, nrmS + ((c-1) & 1)*64,
                     segbase + (c-1)*BN, tv, ti);
        __syncthreads();          // selection done; scores buffer free

        #pragma unroll
        for (int mt = 0; mt < 2; ++mt)
            #pragma unroll
            for (int nt = 0; nt < 2; ++nt)
                #pragma unroll
                for (int e = 0; e < 4; ++e) {
                    int row = wm*32 + mt*16 + (lane >> 2) + ((e >> 1) << 3);
                    int col = wn*16 + nt*8 + ((lane & 3) << 1) + (e & 1);
                    scS[row*65 + col] = (float)acc[mt][nt][e];   // exact (<2^24)
                }
        if (c >= 1 && tid < 64)   // stage norms for chunk c -> slot c&1
            nrmS[(c & 1)*64 + tid] = __ldg(&g_dbnorm[segbase + c*BN + tid]);
    }
    __syncthreads();
    if (tid < 128) {
        select64(scS + tid*65, nrmS + ((NCHUNKS-1) & 1)*64,
                 segbase + (NCHUNKS-1)*BN, tv, ti);
        size_t base = ((size_t)(m0 + tid)*NSEG + blockIdx.y)*NCAND;
        #pragma unroll
        for (int i = 0; i < NCAND; ++i) { g_cv[base + i] = tv[i]; g_ci[base + i] = ti[i]; }
    }
}

// ---------------- LLE (unchanged, proven: exact fp32 rescore of top-32) ----------------
__global__ __launch_bounds__(128)
void lle_kernel(const float* __restrict__ x, const float* __restrict__ db,
                float* __restrict__ out) {
    __shared__ float xs[512];
    __shared__ float nb[10*520];
    __shared__ float cv[128];
    __shared__ int   ci[128];
    __shared__ int   psel[NPRE];
    __shared__ float pd[NPRE];
    __shared__ float G[9][10];
    __shared__ float w[9];
    __shared__ int   sel[10];

    const int q = blockIdx.x, tid = threadIdx.x;
    const int warp = tid >> 5, lane = tid & 31;
    size_t cb = (size_t)q*NSEG*NCAND;
    cv[tid] = g_cv[cb + tid];
    ci[tid] = g_ci[cb + tid];
    for (int n = tid; n < 512; n += 128) xs[n] = x[(size_t)q*512 + n];
    __syncthreads();

    if (tid == 0) {   // approx preselect top-NPRE of 128
        float bv[NPRE]; int bi[NPRE];
        #pragma unroll
        for (int i = 0; i < NPRE; ++i) { bv[i] = __int_as_float(0x7f800000); bi[i] = 0x7fffffff; }
        for (int c = 0; c < 128; ++c) {
            float v = cv[c]; int id = ci[c];
            if (v < bv[NPRE-1]) {
                int p = NPRE-1;
                while (p > 0 && bv[p-1] > v) { bv[p] = bv[p-1]; bi[p] = bi[p-1]; --p; }
                bv[p] = v; bi[p] = id;
            }
        }
        #pragma unroll
        for (int i = 0; i < NPRE; ++i) psel[i] = bi[i];
    }
    __syncthreads();

    for (int c = warp*8; c < warp*8 + 8; ++c) {   // exact fp32 rescore
        const float* row = db + (size_t)psel[c]*512;
        float acc = 0.f;
        #pragma unroll
        for (int j = 0; j < 16; ++j) {
            int n = lane + 32*j;
            float v = row[n] - xs[n];
            acc = fmaf(v, v, acc);
        }
        #pragma unroll
        for (int o = 16; o; o >>= 1) acc += __shfl_xor_sync(0xffffffffu, acc, o);
        if (lane == 0) pd[c] = acc;
    }
    __syncthreads();

    if (tid == 0) {   // exact ordered top-10 (d asc, idx asc)
        float bv[10]; int bi[10];
        #pragma unroll
        for (int i = 0; i < 10; ++i) { bv[i] = __int_as_float(0x7f800000); bi[i] = 0x7fffffff; }
        for (int c = 0; c < NPRE; ++c) {
            float v = pd[c]; int id = psel[c];
            if (v < bv[9] || (v == bv[9] && id < bi[9])) {
                int p = 9;
                while (p > 0 && (bv[p-1] > v || (bv[p-1] == v && bi[p-1] > id))) {
                    bv[p] = bv[p-1]; bi[p] = bi[p-1]; --p;
                }
                bv[p] = v; bi[p] = id;
            }
        }
        #pragma unroll
        for (int i = 0; i < 10; ++i) sel[i] = bi[i];
    }
    __syncthreads();

    for (int r = 0; r < 10; ++r) {
        const float* row = db + (size_t)sel[r]*512;
        for (int n = tid; n < 512; n += 128) nb[r*520 + n] = row[n];
    }
    __syncthreads();

    if (tid < 90) {
        float accv = 0.f;
        if (tid < 81) {
            int i = tid / 9, j = tid % 9;
            const float* ai = nb + (i+1)*520;
            const float* aj = nb + (j+1)*520;
            for (int n = 0; n < 512; ++n) {
                float f0 = nb[n];
                accv += (ai[n]-f0)*(aj[n]-f0);
            }
            G[i][j] = accv;
        } else {
            int i = tid - 81;
            const float* ai = nb + (i+1)*520;
            for (int n = 0; n < 512; ++n) {
                float f0 = nb[n];
                accv += (ai[n]-f0)*(xs[n]-f0);
            }
            G[i][9] = accv;
        }
    }
    __syncthreads();

    if (tid == 0) {
        for (int k = 0; k < 9; ++k) {
            int p = k;
            for (int r = k+1; r < 9; ++r)
                if (fabsf(G[r][k]) > fabsf(G[p][k])) p = r;
            if (p != k)
                for (int c = k; c < 10; ++c) {
                    float t = G[k][c]; G[k][c] = G[p][c]; G[p][c] = t;
                }
            float inv = 1.f / G[k][k];
            for (int r = k+1; r < 9; ++r) {
                float f = G[r][k] * inv;
                for (int c = k; c < 10; ++c) G[r][c] -= f*G[k][c];
            }
        }
        for (int k = 8; k >= 0; --k) {
            float s = G[k][9];
            for (int c = k+1; c < 9; ++c) s -= G[k][c]*w[c];
            w[k] = s / G[k][k];
        }
    }
    __syncthreads();

    float w0 = 1.f;
    #pragma unroll
    for (int k = 0; k < 9; ++k) w0 -= w[k];
    for (int n = tid; n < 512; n += 128) {
        float fuse = w0 * nb[n];
        #pragma unroll
        for (int k = 0; k < 9; ++k) fuse += w[k]*nb[(k+1)*520 + n];
        out[(size_t)q*512 + n] = 0.2f*xs[n] + 0.8f*fuse;
    }
}

extern "C" void kernel_launch(void* const* d_in, const int* in_sizes, int n_in,
                              void* d_out, int out_size) {
    const float* x  = (const float*)d_in[0];
    const float* db = (const float*)d_in[1];
    float* out = (float*)d_out;

    cudaFuncSetAttribute(score_topk_kernel,
        cudaFuncAttributeMaxDynamicSharedMemorySize, SMEM_SC_TOTAL);

    conv_x_kernel<<<(M_Q*KDIM + 255)/256, 256>>>(x);
    conv_db_kernel<<<NPAD, 128>>>(db);
    score_topk_kernel<<<dim3(M_Q/BM, NSEG), 512, SMEM_SC_TOTAL>>>();
    lle_kernel<<<M_Q, 128>>>(x, db, out);
}